// round 10
// baseline (speedup 1.0000x reference)
#include <cuda_runtime.h>
#include <math_constants.h>

#define NTRK 4096
#define NB 64
#define NBINS (NB * NB)
#define FULLMASK 0xffffffffu
#define THREADS 1024
#define TRACKS_PER_BLOCK 32

// fixed bbox (exact for any input via clamping; bound argument in search)
#define BB_MIN (-6.0f)
#define BB_W   (12.0f)
#define CW     (BB_W / (float)NB)        // 0.1875, exact in fp32
#define INVW   ((float)NB / BB_W)
#define EPSB   0.0005f                   // fp safety margin

// ---- device scratch (static: no allocation) ----
__device__ int    g_cnt[NBINS];
__device__ int    g_cur[NBINS];
__device__ int    g_ofs[NBINS + 1];
__device__ int    g_bin[NTRK];
__device__ float4 g_pk[NTRK];            // sorted: x, y, bits(pid), pad

// smem layout for search kernel
#define SM_PTS_OFF  0                    // float4[4096] = 65536
#define SM_OFS_OFF  65536                // int[4097]    = 16388
#define SM_TOTAL    (65536 + 16400)

// lexicographic (d2, idx) insert into sorted-4 list; exact top_k tie-break.
#define LESSI(da, ja, db, jb) (((da) < (db)) || ((da) == (db) && (ja) < (jb)))
#define LEX_INSERT(dv, jv)                                         \
    if (LESSI(dv, jv, s3, i3)) {                                   \
        if (LESSI(dv, jv, s1, i1)) {                               \
            s3 = s2; i3 = i2; s2 = s1; i2 = i1;                    \
            if (LESSI(dv, jv, s0, i0)) { s1 = s0; i1 = i0; s0 = (dv); i0 = (jv); } \
            else                       { s1 = (dv); i1 = (jv); }   \
        } else {                                                   \
            if (LESSI(dv, jv, s2, i2)) { s3 = s2; i3 = i2; s2 = (dv); i2 = (jv); } \
            else                       { s3 = (dv); i3 = (jv); }   \
        }                                                          \
    }

#define PROC_PT(p_)                                                \
    do {                                                           \
        float4 t_ = s_pts[p_];                                     \
        int pj_ = __float_as_int(t_.z);                            \
        float dx_ = t_.x - qx, dy_ = t_.y - qy;                    \
        float dd_ = fmaf(dx_, dx_, dy_ * dy_);                     \
        if (pj_ != i) { LEX_INSERT(dd_, pj_); }                    \
    } while (0)

// ============================================================================
// K0: zero bin counters (graph replays require re-zeroing every launch)
// ============================================================================
__global__ void k0_zero() {
    int c = blockIdx.x * blockDim.x + threadIdx.x;
    if (c < NBINS) g_cnt[c] = 0;
}

// ============================================================================
// K1: histogram — one thread per point, global atomics (4096 total chip-wide)
// ============================================================================
__global__ void k1_hist(const float2* __restrict__ obs2, int n) {
    int p = blockIdx.x * blockDim.x + threadIdx.x;
    if (p >= n) return;
    float2 v = obs2[p];
    int bx = min(NB - 1, max(0, (int)((v.x - BB_MIN) * INVW)));
    int by = min(NB - 1, max(0, (int)((v.y - BB_MIN) * INVW)));
    int b = by * NB + bx;
    g_bin[p] = b;
    atomicAdd(&g_cnt[b], 1);
}

// ============================================================================
// K2: exclusive scan over 4096 counts (single block, 2-level shuffle scan)
// ============================================================================
__global__ __launch_bounds__(THREADS) void k2_scan(int n) {
    __shared__ int s_wsum[32];
    const int t = threadIdx.x;
    const int lane = t & 31;
    const int warp = t >> 5;

    int c4[4];
    #pragma unroll
    for (int k = 0; k < 4; ++k) c4[k] = g_cnt[4 * t + k];
    int tot = c4[0] + c4[1] + c4[2] + c4[3];
    int incl = tot;
    #pragma unroll
    for (int off = 1; off < 32; off <<= 1) {
        int v = __shfl_up_sync(FULLMASK, incl, off);
        if (lane >= off) incl += v;
    }
    if (lane == 31) s_wsum[warp] = incl;
    __syncthreads();
    if (warp == 0) {
        int v = s_wsum[lane];
        int wi = v;
        #pragma unroll
        for (int off = 1; off < 32; off <<= 1) {
            int u = __shfl_up_sync(FULLMASK, wi, off);
            if (lane >= off) wi += u;
        }
        s_wsum[lane] = wi - v;   // exclusive warp base
    }
    __syncthreads();

    int run = s_wsum[warp] + (incl - tot);
    #pragma unroll
    for (int k = 0; k < 4; ++k) {
        g_ofs[4 * t + k] = run;
        g_cur[4 * t + k] = run;
        run += c4[k];
    }
    if (t == THREADS - 1) g_ofs[NBINS] = run;
}

// ============================================================================
// K3: scatter points into bin-sorted packed array
// ============================================================================
__global__ void k3_scatter(const float2* __restrict__ obs2, int n) {
    int p = blockIdx.x * blockDim.x + threadIdx.x;
    if (p >= n) return;
    float2 v = obs2[p];
    int pos = atomicAdd(&g_cur[g_bin[p]], 1);
    g_pk[pos] = make_float4(v.x, v.y, __int_as_float(p), 0.0f);
}

// ============================================================================
// K4: search — copy sorted grid into SMEM (coalesced, no atomics), then
//     one warp per track: rect-expansion kNN + fused Linear/ReLU
// ============================================================================
__global__ __launch_bounds__(THREADS)
void k4_search(const float2* __restrict__ obs1,
               const float2* __restrict__ obs2,
               const float* __restrict__ W,
               const float* __restrict__ bias,
               float* __restrict__ out,
               int n)
{
    extern __shared__ char smem_raw[];
    float4* s_pts = (float4*)(smem_raw + SM_PTS_OFF);
    int*    s_ofs = (int*)   (smem_raw + SM_OFS_OFF);   // [NBINS+1]

    const int t    = threadIdx.x;
    const int lane = t & 31;
    const int warp = t >> 5;

    // coalesced copy of the prebuilt grid into this block's SMEM
    for (int p = t; p < n; p += THREADS) s_pts[p] = g_pk[p];
    for (int c = t; c < NBINS + 1; c += THREADS) s_ofs[c] = g_ofs[c];
    __syncthreads();

    const int i = blockIdx.x * TRACKS_PER_BLOCK + warp;
    if (i >= n) return;

    const float2 q = obs2[i];
    const float qx = q.x, qy = q.y;

    const int cx = min(NB - 1, max(0, (int)((qx - BB_MIN) * INVW)));
    const int cy = min(NB - 1, max(0, (int)((qy - BB_MIN) * INVW)));

    float s0 = CUDART_INF_F, s1 = CUDART_INF_F, s2 = CUDART_INF_F, s3 = CUDART_INF_F;
    int   i0 = n, i1 = n, i2 = n, i3 = n;

    // initial 3x3 rect: each row is a contiguous span, scanned lane-parallel
    int x0 = max(cx - 1, 0), x1 = min(cx + 1, NB - 1);
    int y0 = max(cy - 1, 0), y1 = min(cy + 1, NB - 1);
    for (int y = y0; y <= y1; ++y) {
        int r = y * NB;
        int bg = s_ofs[r + x0], en = s_ofs[r + x1 + 1];
        for (int p = bg + lane; p < en; p += 32) PROC_PT(p);
    }

    while (true) {
        // lower bound on distance to any unprocessed point. Grid-edge sides
        // contribute +inf: all points (incl. clamped outliers) live in bins
        // 0..NB-1, and a clamped outlier lies farther out than its bin's
        // nominal region, so interior-side bounds remain valid lower bounds.
        float bl = (x0 > 0)      ? (qx - (BB_MIN + (float)x0 * CW))       : CUDART_INF_F;
        float br = (x1 < NB - 1) ? ((BB_MIN + (float)(x1 + 1) * CW) - qx) : CUDART_INF_F;
        float bd = (y0 > 0)      ? (qy - (BB_MIN + (float)y0 * CW))       : CUDART_INF_F;
        float bu = (y1 < NB - 1) ? ((BB_MIN + (float)(y1 + 1) * CW) - qy) : CUDART_INF_F;
        float bmin = fminf(fminf(bl, br), fminf(bd, bu));

        if (isinf(bmin)) break;   // rect covers entire grid

        float be = fmaxf(bmin - EPSB, 0.0f);
        float b2 = be * be;
        // exact termination: >=4 candidates (disjoint across lanes) with d2<=b2
        int cnt = (s3 <= b2) ? 4 : (s2 <= b2) ? 3 : (s1 <= b2) ? 2 : (s0 <= b2) ? 1 : 0;
        if (__reduce_add_sync(FULLMASK, cnt) >= 4) break;

        // U = min over lanes of s3 (positive floats / +inf are int-ordered)
        float U = __uint_as_float(__reduce_min_sync(FULLMASK, __float_as_uint(s3)));

        int nx0, nx1, ny0, ny1;
        if (U < CUDART_INF_F) {
            // jump: final answer lies within radius sqrt(U)+eps of q
            float ru = sqrtf(U) + EPSB;
            nx0 = min(x0, max(0,      (int)((qx - ru - BB_MIN) * INVW)));
            nx1 = max(x1, min(NB - 1, (int)((qx + ru - BB_MIN) * INVW)));
            ny0 = min(y0, max(0,      (int)((qy - ru - BB_MIN) * INVW)));
            ny1 = max(y1, min(NB - 1, (int)((qy + ru - BB_MIN) * INVW)));
            if (nx0 == x0 && nx1 == x1 && ny0 == y0 && ny1 == y1) {
                nx0 = max(x0 - 1, 0); nx1 = min(x1 + 1, NB - 1);
                ny0 = max(y0 - 1, 0); ny1 = min(y1 + 1, NB - 1);
            }
        } else {
            // sparse neighborhood: stride 2 across empty space
            nx0 = max(x0 - 2, 0); nx1 = min(x1 + 2, NB - 1);
            ny0 = max(y0 - 2, 0); ny1 = min(y1 + 2, NB - 1);
        }

        // process delta region, one lane per row (rect-height independent)
        for (int yy = ny0 + lane; yy <= ny1; yy += 32) {
            int r = yy * NB;
            if (yy < y0 || yy > y1) {
                int bg = s_ofs[r + nx0], en = s_ofs[r + nx1 + 1];
                for (int p = bg; p < en; ++p) PROC_PT(p);
            } else {
                if (nx0 < x0) {
                    int bg = s_ofs[r + nx0], en = s_ofs[r + x0];
                    for (int p = bg; p < en; ++p) PROC_PT(p);
                }
                if (nx1 > x1) {
                    int bg = s_ofs[r + x1 + 1], en = s_ofs[r + nx1 + 1];
                    for (int p = bg; p < en; ++p) PROC_PT(p);
                }
            }
        }
        x0 = nx0; x1 = nx1; y0 = ny0; y1 = ny1;
    }

    // butterfly merge: every lane ends with identical global top-4
    #pragma unroll
    for (int off = 16; off > 0; off >>= 1) {
        float t0 = __shfl_xor_sync(FULLMASK, s0, off);
        float t1 = __shfl_xor_sync(FULLMASK, s1, off);
        float t2 = __shfl_xor_sync(FULLMASK, s2, off);
        float t3 = __shfl_xor_sync(FULLMASK, s3, off);
        int   u0 = __shfl_xor_sync(FULLMASK, i0, off);
        int   u1 = __shfl_xor_sync(FULLMASK, i1, off);
        int   u2 = __shfl_xor_sync(FULLMASK, i2, off);
        int   u3 = __shfl_xor_sync(FULLMASK, i3, off);
        LEX_INSERT(t0, u0);
        LEX_INSERT(t1, u1);
        LEX_INSERT(t2, u2);
        LEX_INSERT(t3, u3);
    }

    // epilogue: lane = k*8 + e computes out[i][k*8 + e]
    const int k = lane >> 3;
    const int e = lane & 7;
    int nj = (k == 0) ? i0 : (k == 1) ? i1 : (k == 2) ? i2 : i3;
    if (nj >= n) nj = (i == 0) ? 1 : 0;   // degenerate-n safety

    float2 pj  = obs2[nj];
    float2 o1j = obs1[nj];
    float2 o1i = obs1[i];

    float rpx = pj.x - qx;
    float rpy = pj.y - qy;
    float rvx = (pj.x - o1j.x) - (qx - o1i.x);
    float rvy = (pj.y - o1j.y) - (qy - o1i.y);

    float acc = bias[e];
    acc = fmaf(rpx, W[0 * 8 + e], acc);
    acc = fmaf(rpy, W[1 * 8 + e], acc);
    acc = fmaf(rvx, W[2 * 8 + e], acc);
    acc = fmaf(rvy, W[3 * 8 + e], acc);

    out[i * 32 + lane] = fmaxf(acc, 0.0f);
}

extern "C" void kernel_launch(void* const* d_in, const int* in_sizes, int n_in,
                              void* d_out, int out_size) {
    const float2* obs1 = (const float2*)d_in[0];  // [N, 2]
    const float2* obs2 = (const float2*)d_in[1];  // [N, 2]
    const float*  W    = (const float*)d_in[2];   // [4, 8]
    const float*  b    = (const float*)d_in[3];   // [8]
    float* out = (float*)d_out;                    // [N, 32]

    int n = in_sizes[0] / 2;
    if (n > NTRK) n = NTRK;

    cudaFuncSetAttribute(k4_search,
                         cudaFuncAttributeMaxDynamicSharedMemorySize,
                         SM_TOTAL);

    k0_zero<<<(NBINS + 1023) / 1024, 1024>>>();
    k1_hist<<<(n + 1023) / 1024, 1024>>>(obs2, n);
    k2_scan<<<1, THREADS>>>(n);
    k3_scatter<<<(n + 1023) / 1024, 1024>>>(obs2, n);
    int blocks = (n + TRACKS_PER_BLOCK - 1) / TRACKS_PER_BLOCK;
    k4_search<<<blocks, THREADS, SM_TOTAL>>>(obs1, obs2, W, b, out, n);
}

// round 11
// speedup vs baseline: 1.5458x; 1.5458x over previous
#include <cuda_runtime.h>
#include <math_constants.h>

#define NTRK 4096
#define NB 64
#define NBINS (NB * NB)
#define FULLMASK 0xffffffffu
#define THREADS 1024
#define TRACKS_PER_BLOCK 32

// fixed bbox (exact for any input via clamping; bound argument below)
#define BB_MIN (-6.0f)
#define BB_W   (12.0f)
#define CW     (BB_W / (float)NB)        // 0.1875, exact in fp32
#define INVW   ((float)NB / BB_W)
#define EPSB   0.0005f                   // fp safety margin

// dynamic smem layout: packed points (x, y, pid_bits, pad) + offsets
#define SM_PTS_OFF  0                          // float4[4096] = 65536
#define SM_OFS_OFF  65536                      // int[4097]    = 16388
#define SM_WSUM_OFF (65536 + 16400)            // int[32]      = 128
#define SM_TOTAL    (65536 + 16400 + 128)

// lexicographic (d2, idx) insert into sorted-4 list; exact top_k tie-break.
// Order-independent, so any point processing order is exact.
#define LESSI(da, ja, db, jb) (((da) < (db)) || ((da) == (db) && (ja) < (jb)))
#define LEX_INSERT(dv, jv)                                         \
    if (LESSI(dv, jv, s3, i3)) {                                   \
        if (LESSI(dv, jv, s1, i1)) {                               \
            s3 = s2; i3 = i2; s2 = s1; i2 = i1;                    \
            if (LESSI(dv, jv, s0, i0)) { s1 = s0; i1 = i0; s0 = (dv); i0 = (jv); } \
            else                       { s1 = (dv); i1 = (jv); }   \
        } else {                                                   \
            if (LESSI(dv, jv, s2, i2)) { s3 = s2; i3 = i2; s2 = (dv); i2 = (jv); } \
            else                       { s3 = (dv); i3 = (jv); }   \
        }                                                          \
    }

// one candidate: single LDS.128
#define PROC_PT(p_)                                                \
    do {                                                           \
        float4 t_ = s_pts[p_];                                     \
        int pj_ = __float_as_int(t_.z);                            \
        float dx_ = t_.x - qx, dy_ = t_.y - qy;                    \
        float dd_ = fmaf(dx_, dx_, dy_ * dy_);                     \
        if (pj_ != i) { LEX_INSERT(dd_, pj_); }                    \
    } while (0)

__global__ __launch_bounds__(THREADS)
void nn_pool_fused(const float2* __restrict__ obs1,
                   const float2* __restrict__ obs2,
                   const float* __restrict__ W,
                   const float* __restrict__ bias,
                   float* __restrict__ out,
                   int n)
{
    extern __shared__ char smem_raw[];
    float4* s_pts  = (float4*)(smem_raw + SM_PTS_OFF);
    int*    s_ofs  = (int*)   (smem_raw + SM_OFS_OFF);   // [NBINS+1]
    int*    s_wsum = (int*)   (smem_raw + SM_WSUM_OFF);

    const int t    = threadIdx.x;
    const int lane = t & 31;
    const int warp = t >> 5;

    // ---------------- per-block grid build (all in SMEM) ----------------
    // Phase A: zero counts, then histogram. The atomicAdd return value IS
    // the point's within-bin rank -> scatter later needs NO atomics.
    for (int c = t; c < NBINS + 1; c += THREADS) s_ofs[c] = 0;
    __syncthreads();

    float px[4], py[4];
    int   bins[4], rank[4];
    #pragma unroll
    for (int k = 0; k < 4; ++k) {
        int p = t + k * THREADS;
        bins[k] = -1;
        if (p < n) {
            float2 v = obs2[p];
            px[k] = v.x; py[k] = v.y;
            int bx = min(NB - 1, max(0, (int)((v.x - BB_MIN) * INVW)));
            int by = min(NB - 1, max(0, (int)((v.y - BB_MIN) * INVW)));
            bins[k] = by * NB + bx;
            rank[k] = atomicAdd(&s_ofs[bins[k]], 1);
        }
    }
    __syncthreads();

    // Phase B: exclusive scan over 4096 counts (2-level shuffle scan).
    // Reads counts into registers first, then overwrites s_ofs with offsets.
    int c4[4];
    #pragma unroll
    for (int k = 0; k < 4; ++k) c4[k] = s_ofs[4 * t + k];
    int tot = c4[0] + c4[1] + c4[2] + c4[3];
    int incl = tot;
    #pragma unroll
    for (int off = 1; off < 32; off <<= 1) {
        int v = __shfl_up_sync(FULLMASK, incl, off);
        if (lane >= off) incl += v;
    }
    if (lane == 31) s_wsum[warp] = incl;
    __syncthreads();
    if (warp == 0) {
        int v = s_wsum[lane];
        int wi = v;
        #pragma unroll
        for (int off = 1; off < 32; off <<= 1) {
            int u = __shfl_up_sync(FULLMASK, wi, off);
            if (lane >= off) wi += u;
        }
        s_wsum[lane] = wi - v;   // exclusive warp base
    }
    __syncthreads();

    int run = s_wsum[warp] + (incl - tot);
    #pragma unroll
    for (int k = 0; k < 4; ++k) {
        s_ofs[4 * t + k] = run;    // final exclusive offset of bin 4t+k
        run += c4[k];
    }
    if (t == THREADS - 1) s_ofs[NBINS] = run;
    __syncthreads();

    // Phase C: atomic-free scatter — pos = bin offset + captured rank
    #pragma unroll
    for (int k = 0; k < 4; ++k) {
        if (bins[k] >= 0) {
            int pos = s_ofs[bins[k]] + rank[k];
            s_pts[pos] = make_float4(px[k], py[k],
                                     __int_as_float(t + k * THREADS), 0.0f);
        }
    }
    __syncthreads();

    // ---------------- search: one warp per track, all SMEM ----------------
    const int i = blockIdx.x * TRACKS_PER_BLOCK + warp;
    if (i >= n) return;

    const float2 q = obs2[i];
    const float qx = q.x, qy = q.y;

    const int cx = min(NB - 1, max(0, (int)((qx - BB_MIN) * INVW)));
    const int cy = min(NB - 1, max(0, (int)((qy - BB_MIN) * INVW)));

    float s0 = CUDART_INF_F, s1 = CUDART_INF_F, s2 = CUDART_INF_F, s3 = CUDART_INF_F;
    int   i0 = n, i1 = n, i2 = n, i3 = n;

    // initial 3x3 rect: each row is a contiguous span, scanned lane-parallel
    int x0 = max(cx - 1, 0), x1 = min(cx + 1, NB - 1);
    int y0 = max(cy - 1, 0), y1 = min(cy + 1, NB - 1);
    for (int y = y0; y <= y1; ++y) {
        int r = y * NB;
        int bg = s_ofs[r + x0], en = s_ofs[r + x1 + 1];
        for (int p = bg + lane; p < en; p += 32) PROC_PT(p);
    }

    while (true) {
        // lower bound on distance to any unprocessed point. Grid-edge sides
        // contribute +inf: all points (incl. clamped outliers) live in bins
        // 0..NB-1, and a clamped outlier lies farther out than its bin's
        // nominal region, so interior-side bounds remain valid lower bounds.
        float bl = (x0 > 0)      ? (qx - (BB_MIN + (float)x0 * CW))       : CUDART_INF_F;
        float br = (x1 < NB - 1) ? ((BB_MIN + (float)(x1 + 1) * CW) - qx) : CUDART_INF_F;
        float bd = (y0 > 0)      ? (qy - (BB_MIN + (float)y0 * CW))       : CUDART_INF_F;
        float bu = (y1 < NB - 1) ? ((BB_MIN + (float)(y1 + 1) * CW) - qy) : CUDART_INF_F;
        float bmin = fminf(fminf(bl, br), fminf(bd, bu));

        if (isinf(bmin)) break;   // rect covers entire grid

        float be = fmaxf(bmin - EPSB, 0.0f);
        float b2 = be * be;
        // exact termination: >=4 candidates (disjoint across lanes) with d2<=b2
        int cnt = (s3 <= b2) ? 4 : (s2 <= b2) ? 3 : (s1 <= b2) ? 2 : (s0 <= b2) ? 1 : 0;
        if (__reduce_add_sync(FULLMASK, cnt) >= 4) break;

        // U = min over lanes of s3 (positive floats / +inf are int-ordered)
        float U = __uint_as_float(__reduce_min_sync(FULLMASK, __float_as_uint(s3)));

        int nx0, nx1, ny0, ny1;
        if (U < CUDART_INF_F) {
            // jump: final answer lies within radius sqrt(U)+eps of q
            float ru = sqrtf(U) + EPSB;
            nx0 = min(x0, max(0,      (int)((qx - ru - BB_MIN) * INVW)));
            nx1 = max(x1, min(NB - 1, (int)((qx + ru - BB_MIN) * INVW)));
            ny0 = min(y0, max(0,      (int)((qy - ru - BB_MIN) * INVW)));
            ny1 = max(y1, min(NB - 1, (int)((qy + ru - BB_MIN) * INVW)));
            if (nx0 == x0 && nx1 == x1 && ny0 == y0 && ny1 == y1) {
                // fp edge: force progress
                nx0 = max(x0 - 1, 0); nx1 = min(x1 + 1, NB - 1);
                ny0 = max(y0 - 1, 0); ny1 = min(y1 + 1, NB - 1);
            }
        } else {
            // sparse neighborhood: stride 2 across empty space
            nx0 = max(x0 - 2, 0); nx1 = min(x1 + 2, NB - 1);
            ny0 = max(y0 - 2, 0); ny1 = min(y1 + 2, NB - 1);
        }

        // process delta region, one lane per row (rect-height independent)
        for (int yy = ny0 + lane; yy <= ny1; yy += 32) {
            int r = yy * NB;
            if (yy < y0 || yy > y1) {
                int bg = s_ofs[r + nx0], en = s_ofs[r + nx1 + 1];
                for (int p = bg; p < en; ++p) PROC_PT(p);
            } else {
                if (nx0 < x0) {
                    int bg = s_ofs[r + nx0], en = s_ofs[r + x0];
                    for (int p = bg; p < en; ++p) PROC_PT(p);
                }
                if (nx1 > x1) {
                    int bg = s_ofs[r + x1 + 1], en = s_ofs[r + nx1 + 1];
                    for (int p = bg; p < en; ++p) PROC_PT(p);
                }
            }
        }
        x0 = nx0; x1 = nx1; y0 = ny0; y1 = ny1;
    }

    // butterfly merge: every lane ends with identical global top-4
    #pragma unroll
    for (int off = 16; off > 0; off >>= 1) {
        float t0 = __shfl_xor_sync(FULLMASK, s0, off);
        float t1 = __shfl_xor_sync(FULLMASK, s1, off);
        float t2 = __shfl_xor_sync(FULLMASK, s2, off);
        float t3 = __shfl_xor_sync(FULLMASK, s3, off);
        int   u0 = __shfl_xor_sync(FULLMASK, i0, off);
        int   u1 = __shfl_xor_sync(FULLMASK, i1, off);
        int   u2 = __shfl_xor_sync(FULLMASK, i2, off);
        int   u3 = __shfl_xor_sync(FULLMASK, i3, off);
        LEX_INSERT(t0, u0);
        LEX_INSERT(t1, u1);
        LEX_INSERT(t2, u2);
        LEX_INSERT(t3, u3);
    }

    // epilogue: lane = k*8 + e computes out[i][k*8 + e]
    const int k = lane >> 3;
    const int e = lane & 7;
    int nj = (k == 0) ? i0 : (k == 1) ? i1 : (k == 2) ? i2 : i3;
    if (nj >= n) nj = (i == 0) ? 1 : 0;   // degenerate-n safety

    float2 pj  = obs2[nj];
    float2 o1j = obs1[nj];
    float2 o1i = obs1[i];

    float rpx = pj.x - qx;
    float rpy = pj.y - qy;
    float rvx = (pj.x - o1j.x) - (qx - o1i.x);
    float rvy = (pj.y - o1j.y) - (qy - o1i.y);

    float acc = bias[e];
    acc = fmaf(rpx, W[0 * 8 + e], acc);
    acc = fmaf(rpy, W[1 * 8 + e], acc);
    acc = fmaf(rvx, W[2 * 8 + e], acc);
    acc = fmaf(rvy, W[3 * 8 + e], acc);

    out[i * 32 + lane] = fmaxf(acc, 0.0f);
}

extern "C" void kernel_launch(void* const* d_in, const int* in_sizes, int n_in,
                              void* d_out, int out_size) {
    const float2* obs1 = (const float2*)d_in[0];  // [N, 2]
    const float2* obs2 = (const float2*)d_in[1];  // [N, 2]
    const float*  W    = (const float*)d_in[2];   // [4, 8]
    const float*  b    = (const float*)d_in[3];   // [8]
    float* out = (float*)d_out;                    // [N, 32]

    int n = in_sizes[0] / 2;
    if (n > NTRK) n = NTRK;

    static bool attr_set = false;
    if (!attr_set) {
        cudaFuncSetAttribute(nn_pool_fused,
                             cudaFuncAttributeMaxDynamicSharedMemorySize,
                             SM_TOTAL);
        attr_set = true;
    }

    int blocks = (n + TRACKS_PER_BLOCK - 1) / TRACKS_PER_BLOCK;
    nn_pool_fused<<<blocks, THREADS, SM_TOTAL>>>(obs1, obs2, W, b, out, n);
}